// round 1
// baseline (speedup 1.0000x reference)
#include <cuda_runtime.h>
#include <math.h>

#define BQ 8
#define CC 1024
#define DD 512
#define MROWS 32768            // B*N = 16*2048
#define EPSF 1e-6f

// ---- scratch (device globals; no allocation allowed) ----
__device__ float g_residual[(size_t)MROWS * DD];   // 64 MB
__device__ float g_cbsq[BQ * CC];
__device__ int   g_idx[MROWS];
__device__ float g_loss[BQ];

// ---------------------------------------------------------------------------
// init: residual = x, zero quantized output section, zero losses
// ---------------------------------------------------------------------------
__global__ void init_kernel(const float* __restrict__ x, float* __restrict__ out_q) {
    size_t i  = (size_t)blockIdx.x * blockDim.x + threadIdx.x;
    size_t n4 = (size_t)MROWS * DD / 4;
    const float4* x4 = (const float4*)x;
    float4* r4 = (float4*)g_residual;
    float4* o4 = (float4*)out_q;
    float4 z = make_float4(0.f, 0.f, 0.f, 0.f);
    for (size_t k = i; k < n4; k += (size_t)gridDim.x * blockDim.x) {
        r4[k] = x4[k];
        o4[k] = z;
    }
    if (i < BQ) g_loss[i] = 0.f;
}

// ---------------------------------------------------------------------------
// cb_sq[q][c] = sum_d codebooks[q][c][d]^2   (one warp per codebook row)
// ---------------------------------------------------------------------------
__global__ void cbsq_kernel(const float* __restrict__ cb) {
    int row  = blockIdx.x * 8 + (threadIdx.x >> 5);   // 0 .. BQ*CC-1
    int lane = threadIdx.x & 31;
    const float4* p = (const float4*)(cb + (size_t)row * DD);
    float s = 0.f;
#pragma unroll
    for (int j = 0; j < 4; j++) {
        float4 v = p[lane + 32 * j];
        s += v.x * v.x + v.y * v.y + v.z * v.z + v.w * v.w;
    }
#pragma unroll
    for (int o = 16; o; o >>= 1) s += __shfl_xor_sync(0xFFFFFFFFu, s, o);
    if (lane == 0) g_cbsq[row] = s;
}

// ---------------------------------------------------------------------------
// Fused distance GEMM + argmin.
// For each row r of g_residual, find argmin_c ( cb_sq[c] - 2 * r.c ).
// Register-blocked SGEMM: BM=128 rows x BN=128 codes per pass, 8x8 per thread,
// looping over 8 code chunks so each block covers all 1024 codes.
// ---------------------------------------------------------------------------
#define BM 128
#define BNC 128
#define BK 16
#define TM 8
#define TN 8

__global__ __launch_bounds__(256) void dist_argmin_kernel(
    const float* __restrict__ cbs, int qi)
{
    __shared__ float As[BK][BM];
    __shared__ float Bs[BK][BNC];
    __shared__ float redV[16][BM];
    __shared__ int   redI[16][BM];

    const float* CB  = cbs + (size_t)qi * CC * DD;
    const float* csq = g_cbsq + qi * CC;

    const int tid = threadIdx.x;
    const int tx  = tid & 15;       // code dimension
    const int ty  = tid >> 4;       // row dimension
    const int rowBase = blockIdx.x * BM;

    float best[TM];
    int   bestI[TM];
#pragma unroll
    for (int i = 0; i < TM; i++) { best[i] = INFINITY; bestI[i] = 0x7fffffff; }

    for (int cc = 0; cc < CC / BNC; cc++) {
        float acc[TM][TN];
#pragma unroll
        for (int i = 0; i < TM; i++)
#pragma unroll
            for (int j = 0; j < TN; j++) acc[i][j] = 0.f;

        for (int kt = 0; kt < DD / BK; kt++) {
            // load A (residual) and B (codebook) tiles, transposed into smem
#pragma unroll
            for (int j = 0; j < 2; j++) {
                int lin = tid + j * 256;          // 0..511
                int ar  = lin >> 2;               // 0..127
                int kv  = (lin & 3) * 4;          // 0,4,8,12
                float4 av = *(const float4*)(g_residual +
                              (size_t)(rowBase + ar) * DD + kt * BK + kv);
                As[kv + 0][ar] = av.x; As[kv + 1][ar] = av.y;
                As[kv + 2][ar] = av.z; As[kv + 3][ar] = av.w;
                float4 bv = *(const float4*)(CB +
                              (size_t)(cc * BNC + ar) * DD + kt * BK + kv);
                Bs[kv + 0][ar] = bv.x; Bs[kv + 1][ar] = bv.y;
                Bs[kv + 2][ar] = bv.z; Bs[kv + 3][ar] = bv.w;
            }
            __syncthreads();

#pragma unroll
            for (int k = 0; k < BK; k++) {
                float a[TM], b[TN];
                float4 t0 = *(const float4*)&As[k][ty * TM];
                float4 t1 = *(const float4*)&As[k][ty * TM + 4];
                a[0]=t0.x; a[1]=t0.y; a[2]=t0.z; a[3]=t0.w;
                a[4]=t1.x; a[5]=t1.y; a[6]=t1.z; a[7]=t1.w;
                float4 u0 = *(const float4*)&Bs[k][tx * TN];
                float4 u1 = *(const float4*)&Bs[k][tx * TN + 4];
                b[0]=u0.x; b[1]=u0.y; b[2]=u0.z; b[3]=u0.w;
                b[4]=u1.x; b[5]=u1.y; b[6]=u1.z; b[7]=u1.w;
#pragma unroll
                for (int i = 0; i < TM; i++)
#pragma unroll
                    for (int j = 0; j < TN; j++)
                        acc[i][j] += a[i] * b[j];
            }
            __syncthreads();
        }

        // fold this code chunk into running argmin
#pragma unroll
        for (int j = 0; j < TN; j++) {
            int code = cc * BNC + tx * TN + j;
            float cq = csq[code];
#pragma unroll
            for (int i = 0; i < TM; i++) {
                float v = cq - 2.f * acc[i][j];
                if (v < best[i] || (v == best[i] && code < bestI[i])) {
                    best[i] = v; bestI[i] = code;
                }
            }
        }
    }

    // cross-thread reduction over the 16 tx slots sharing each row
#pragma unroll
    for (int i = 0; i < TM; i++) {
        redV[tx][ty * TM + i] = best[i];
        redI[tx][ty * TM + i] = bestI[i];
    }
    __syncthreads();
    if (tid < BM) {
        float bv = INFINITY; int bi = 0x7fffffff;
#pragma unroll
        for (int t = 0; t < 16; t++) {
            float v = redV[t][tid];
            int   id = redI[t][tid];
            if (v < bv || (v == bv && id < bi)) { bv = v; bi = id; }
        }
        g_idx[rowBase + tid] = bi;
    }
}

// ---------------------------------------------------------------------------
// Rotation trick + residual/output update + loss + index write. Warp per row.
// ---------------------------------------------------------------------------
__global__ void rotate_kernel(const float* __restrict__ cbs, int qi,
                              float* __restrict__ out_q,
                              float* __restrict__ out_if,
                              int writeIdx, int writeLoss)
{
    __shared__ float ws[8];
    int row  = blockIdx.x * 8 + (threadIdx.x >> 5);
    int lane = threadIdx.x & 31;
    float* zp = g_residual + (size_t)row * DD;
    int idx = g_idx[row];
    const float* qp = cbs + ((size_t)qi * CC + idx) * DD;

    float4 zv[4], qv[4];
    float zz = 0.f, qq = 0.f, zq = 0.f, ll = 0.f;
#pragma unroll
    for (int j = 0; j < 4; j++) {
        zv[j] = ((const float4*)zp)[lane + 32 * j];
        qv[j] = ((const float4*)qp)[lane + 32 * j];
        zz += zv[j].x*zv[j].x + zv[j].y*zv[j].y + zv[j].z*zv[j].z + zv[j].w*zv[j].w;
        qq += qv[j].x*qv[j].x + qv[j].y*qv[j].y + qv[j].z*qv[j].z + qv[j].w*qv[j].w;
        zq += zv[j].x*qv[j].x + zv[j].y*qv[j].y + zv[j].z*qv[j].z + zv[j].w*qv[j].w;
        float dx = qv[j].x - zv[j].x, dy = qv[j].y - zv[j].y;
        float dz = qv[j].z - zv[j].z, dw = qv[j].w - zv[j].w;
        ll += dx*dx + dy*dy + dz*dz + dw*dw;
    }
#pragma unroll
    for (int o = 16; o; o >>= 1) {
        zz += __shfl_xor_sync(0xFFFFFFFFu, zz, o);
        qq += __shfl_xor_sync(0xFFFFFFFFu, qq, o);
        zq += __shfl_xor_sync(0xFFFFFFFFu, zq, o);
        ll += __shfl_xor_sync(0xFFFFFFFFu, ll, o);
    }

    float nz = sqrtf(zz), nq = sqrtf(qq);
    float iz = 1.f / (nz + EPSF), iq = 1.f / (nq + EPSF);
    float s2 = zz * iz * iz + 2.f * zq * iz * iq + qq * iq * iq;
    float A2 = 2.f * (zz * iz + zq * iq) / s2;
    float Bc = 2.f * zz * iz * iq;
    float cz = 1.f - A2 * iz;     // coefficient on z
    float cq = Bc - A2 * iq;      // coefficient on q
    float sc = nq * iz;           // scale

    float* op = out_q + (size_t)row * DD;
#pragma unroll
    for (int j = 0; j < 4; j++) {
        float4 z = zv[j], q = qv[j], t, r, o;
        t.x = (z.x * cz + q.x * cq) * sc;
        t.y = (z.y * cz + q.y * cq) * sc;
        t.z = (z.z * cz + q.z * cq) * sc;
        t.w = (z.w * cz + q.w * cq) * sc;
        r.x = z.x - t.x; r.y = z.y - t.y; r.z = z.z - t.z; r.w = z.w - t.w;
        ((float4*)zp)[lane + 32 * j] = r;
        o = ((float4*)op)[lane + 32 * j];
        o.x += t.x; o.y += t.y; o.z += t.z; o.w += t.w;
        ((float4*)op)[lane + 32 * j] = o;
    }

    if (writeIdx && lane == 0)
        out_if[(size_t)row * BQ + qi] = (float)idx;

    if (writeLoss) {
        if (lane == 0) ws[threadIdx.x >> 5] = ll;
        __syncthreads();
        if (threadIdx.x == 0) {
            float s = 0.f;
#pragma unroll
            for (int w = 0; w < 8; w++) s += ws[w];
            atomicAdd(&g_loss[qi], s);
        }
    }
}

// ---------------------------------------------------------------------------
// finalize: losses = sum / (M*D)
// ---------------------------------------------------------------------------
__global__ void final_kernel(float* __restrict__ out_loss) {
    int i = threadIdx.x;
    if (i < BQ) out_loss[i] = g_loss[i] / (float)((size_t)MROWS * DD);
}

// ---------------------------------------------------------------------------
extern "C" void kernel_launch(void* const* d_in, const int* in_sizes, int n_in,
                              void* d_out, int out_size) {
    const float* x   = (const float*)d_in[0];
    const float* cbs = (const float*)d_in[1];
    // robustness: swap if input order differs
    if (n_in >= 2 && in_sizes[0] == BQ * CC * DD && in_sizes[1] == MROWS * DD) {
        const float* t = x; x = cbs; cbs = t;
    }

    float* out = (float*)d_out;
    const long long qElems = (long long)MROWS * DD;   // 16777216
    const long long iElems = (long long)MROWS * BQ;   // 262144
    float* out_q = out;
    float* out_i = out + qElems;
    float* out_l = out + qElems + iElems;
    int haveIdx  = (out_size >= qElems + iElems) ? 1 : 0;
    int haveLoss = (out_size >= qElems + iElems + BQ) ? 1 : 0;

    init_kernel<<<1024, 256>>>(x, out_q);
    cbsq_kernel<<<BQ * CC / 8, 256>>>(cbs);

    for (int qi = 0; qi < BQ; qi++) {
        dist_argmin_kernel<<<MROWS / BM, 256>>>(cbs, qi);
        rotate_kernel<<<MROWS / 8, 256>>>(cbs, qi, out_q, out_i, haveIdx, haveLoss);
    }

    if (haveLoss) final_kernel<<<1, 32>>>(out_l);
}